// round 15
// baseline (speedup 1.0000x reference)
#include <cuda_runtime.h>
#include <cstdint>

// Problem constants
#define BATCH 2
#define A_    2
#define C_    10
#define HW_   1024
#define NBOX  2048
#define TILE  128
#define LOG2E 1.4426950408889634f
#define PI_F  3.14159265358979323846f

// Output layout: out_scores [0,40960) | bbox [40960,69632) | pp [69632,131072)
#define OUT_BBOX 40960
#define OUT_PP   69632

// Block ranges in the single kernel
#define B_WPACK  80     // [0,80)    wpack
#define B_P1PACK 112    // [80,112)  p1pack
#define B_P1TAIL 128    // [112,128) p1tail
#define B_P0PACK 208    // [128,208) p0pack
#define B_BEV    224    // [208,224) bev
#define B_SCSUM  244    // [224,244) scsum
#define B_COPY   332    // [244,332) copies
#define B_TOTAL  1356   // [332,1356) compute (1024)
#define N_PREP   224u
#define N_SCS    20u
#define N_COMP   1024u

// ---------------- scratch tables (SoA-group layouts) ----------------
__device__ __align__(16) float4 g_bev4[BATCH * 2 * HW_];
__device__ __align__(16) float4 g_pc4[BATCH * 8 * HW_];
__device__ __align__(8)  float2 g_p0f2[BATCH * 5 * HW_];
__device__ float g_scinv[BATCH * C_];

typedef unsigned long long ull;
// partial sums: [h][cell][k][{acc0,acc1,sm0,sm1}]
__device__ __align__(16) ull g_part[2 * NBOX * 5 * 4];
// counters (zero-initialized; self-resetting every launch)
__device__ unsigned g_ctr[3];        // [0]=prep done, [1]=scsum done, [2]=compute finished
__device__ unsigned g_qctr[512];     // per n-quad arrivals (self-reset by combiner)

// ---------------- helpers ----------------
__device__ __forceinline__ float ex2(float x) {
    float y; asm("ex2.approx.f32 %0, %1;" : "=f"(y) : "f"(x)); return y;
}
__device__ __forceinline__ float rcpf(float x) {
    float y; asm("rcp.approx.f32 %0, %1;" : "=f"(y) : "f"(x)); return y;
}
__device__ __forceinline__ ull pk(float a, float b) {
    ull r; asm("mov.b64 %0, {%1,%2};" : "=l"(r) : "f"(a), "f"(b)); return r;
}
__device__ __forceinline__ void upk(ull v, float& a, float& b) {
    asm("mov.b64 {%0,%1}, %2;" : "=f"(a), "=f"(b) : "l"(v));
}
__device__ __forceinline__ ull mul2(ull a, ull b) {
    ull r; asm("mul.rn.f32x2 %0, %1, %2;" : "=l"(r) : "l"(a), "l"(b)); return r;
}
__device__ __forceinline__ ull fma2(ull a, ull b, ull c) {
    ull r; asm("fma.rn.f32x2 %0, %1, %2, %3;" : "=l"(r) : "l"(a), "l"(b), "l"(c)); return r;
}
__device__ __forceinline__ ull add2(ull a, ull b) {
    ull r; asm("add.rn.f32x2 %0, %1, %2;" : "=l"(r) : "l"(a), "l"(b)); return r;
}
__device__ __forceinline__ void cpasync16(uint32_t saddr, const void* g) {
    asm volatile("cp.async.cg.shared.global [%0], [%1], 16;" :: "r"(saddr), "l"(g));
}
__device__ __forceinline__ unsigned ld_acq(const unsigned* p) {
    unsigned v;
    asm volatile("ld.acquire.gpu.global.u32 %0, [%1];" : "=r"(v) : "l"(p) : "memory");
    return v;
}

__device__ __forceinline__ float iou1(float ax1, float ay1, float ax2, float ay2, float aa,
                                      float bx1, float by1, float bx2, float by2, float ba) {
    float ltx = fmaxf(ax1, bx1);
    float lty = fmaxf(ay1, by1);
    float rbx = fminf(ax2, bx2);
    float rby = fminf(ay2, by2);
    float w = fmaxf(rbx - ltx, 0.f);
    float h = fmaxf(rby - lty, 0.f);
    float inter = w * h;
    float uni = fmaxf(aa + ba - inter, 1e-6f);
    return inter * LOG2E * rcpf(uni);
}

// ---------------------------------------------------------------------------
// THE kernel: prep + scsum + copies + compute + combine, one launch.
// ---------------------------------------------------------------------------
__global__ void __launch_bounds__(128, 5) k_all(
        const float* __restrict__ scores,
        const float* __restrict__ bbox,
        const float* __restrict__ pp,
        const float* __restrict__ dec,
        float* __restrict__ out) {
    int blk = blockIdx.x;
    int tid = threadIdx.x;

    if (blk < B_BEV) {
        // ============ prep slices ============
        if (blk < B_WPACK) {
            int i = blk * 128 + tid;          // [0, 10240)
            int b = i / 5120;
            int r = i - b * 5120;
            int k = r >> 10;
            int hw = r & (HW_ - 1);
            int c0 = 2 * k, c1 = 2 * k + 1;
            const float* sb = scores + (size_t)b * 2 * C_ * HW_ + hw;
            float e00 = __expf(sb[(0 * C_ + c0) * HW_]);
            float e10 = __expf(sb[(0 * C_ + c1) * HW_]);
            float e01 = __expf(sb[(1 * C_ + c0) * HW_]);
            float e11 = __expf(sb[(1 * C_ + c1) * HW_]);
            g_pc4[((size_t)b * 8 + k) * HW_ + hw] = make_float4(e00, e10, e01, e11);
        } else if (blk < B_P1PACK) {
            int i = (blk - B_WPACK) * 128 + tid;  // [0, 4096)
            int b = i >> 11;
            int r = i & 2047;
            int g5 = r >> 10;
            int hw = r & (HW_ - 1);
            int cb = 4 * g5;
            const float* pb = pp + (size_t)b * 30 * HW_ + hw;
            float4 v = make_float4(pb[(3 * (cb + 0) + 1) * HW_],
                                   pb[(3 * (cb + 1) + 1) * HW_],
                                   pb[(3 * (cb + 2) + 1) * HW_],
                                   pb[(3 * (cb + 3) + 1) * HW_]);
            g_pc4[((size_t)b * 8 + 5 + g5) * HW_ + hw] = v;
        } else if (blk < B_P1TAIL) {
            int i = (blk - B_P1PACK) * 128 + tid; // [0, 2048)
            int b = i >> 10;
            int hw = i & (HW_ - 1);
            const float* pb = pp + (size_t)b * 30 * HW_ + hw;
            float2 v = make_float2(pb[25 * HW_], pb[28 * HW_]);
            *(float2*)&g_pc4[((size_t)b * 8 + 7) * HW_ + hw].x = v;
        } else if (blk < B_P0PACK) {
            int i = (blk - B_P1TAIL) * 128 + tid; // [0, 10240)
            int b = i / 5120;
            int r = i - b * 5120;
            int k = r >> 10;
            int hw = r & (HW_ - 1);
            const float* pb = pp + (size_t)b * 30 * HW_ + hw;
            float2 v = make_float2(pb[(3 * (2 * k)) * HW_] * LOG2E,
                                   pb[(3 * (2 * k + 1)) * HW_] * LOG2E);
            g_p0f2[((size_t)b * 5 + k) * HW_ + hw] = v;
        } else {
            int i = (blk - B_P0PACK) * 128 + tid; // [0, 2048)
            int b = i >> 10;
            int hw = i & (HW_ - 1);
            float x1a[2], y1a[2], x2a[2], y2a[2], area[2];
#pragma unroll
            for (int a = 0; a < 2; a++) {
                const float* d7 = dec + ((size_t)b * NBOX + hw * 2 + a) * 7;
                float x = d7[0], y = d7[1], dx = d7[3], dy = d7[4], yaw = d7[6];
                float normed = fabsf(yaw - floorf(yaw / PI_F + 0.5f) * PI_F);
                bool sw = normed > 0.25f * PI_F;
                float w = sw ? dy : dx;
                float h = sw ? dx : dy;
                x1a[a] = x - 0.5f * w; y1a[a] = y - 0.5f * h;
                x2a[a] = x + 0.5f * w; y2a[a] = y + 0.5f * h;
                area[a] = (x2a[a] - x1a[a]) * (y2a[a] - y1a[a]);
            }
            float4* bv = g_bev4 + (size_t)b * 2 * HW_ + hw;
            bv[0]   = make_float4(x1a[0], x1a[1], y1a[0], y1a[1]);
            bv[HW_] = make_float4(x2a[0], x2a[1], y2a[0], y2a[1]);
            *(float2*)&g_pc4[((size_t)b * 8 + 7) * HW_ + hw].z = make_float2(area[0], area[1]);
        }
        __syncthreads();
        if (tid == 0) {
            __threadfence();
            atomicAdd(&g_ctr[0], 1u);
        }
        return;
    }

    if (blk < B_SCSUM) {
        // ============ score-softmax denominators ============
        int s = blk - B_BEV;
        int b = s / C_, c = s % C_;
        __shared__ float red[128];
        float acc = 0.f;
        for (int m = tid; m < NBOX; m += 128) {
            int a = m & 1, hw = m >> 1;
            acc += __expf(scores[((b * A_ + a) * C_ + c) * HW_ + hw]);
        }
        red[tid] = acc;
        __syncthreads();
#pragma unroll
        for (int o = 64; o > 0; o >>= 1) {
            if (tid < o) red[tid] += red[tid + o];
            __syncthreads();
        }
        if (tid == 0) {
            g_scinv[b * C_ + c] = 1.0f / red[0];
            __threadfence();
            atomicAdd(&g_ctr[1], 1u);
        }
        return;
    }

    if (blk < B_COPY) {
        // ============ pass-through copies ============
        int base = (blk - B_SCSUM) * 128 + tid;   // [0, 11264)
#pragma unroll
        for (int r = 0; r < 2; r++) {
            int i = base + r * 11264;
            if (i < 7168)
                ((float4*)(out + OUT_BBOX))[i] = ((const float4*)bbox)[i];
            else
                ((float4*)(out + OUT_PP))[i - 7168] = ((const float4*)pp)[i - 7168];
        }
        return;
    }

    // ============ compute: (n-quad, m-half) ============
    __shared__ __align__(16) float4     sb[2][2 * TILE];
    __shared__ __align__(16) ulonglong2 sp[2][8 * TILE];
    __shared__ unsigned s_old;

    // wait for prep
    if (tid == 0) {
        while (ld_acq(&g_ctr[0]) < N_PREP) __nanosleep(64);
    }
    __syncthreads();

    int lane = tid & 31;
    int cb = blk - B_COPY;
    int h = cb & 1;
    int q = cb >> 1;                       // n-quad [0,512)
    int gw = q * 4 + (tid >> 5);           // n-cell [0,2048)
    int b = gw >> 10;
    int hwn = gw & (HW_ - 1);

    float4 ng0 = g_bev4[(size_t)b * 2 * HW_ + hwn];
    float4 ng1 = g_bev4[(size_t)b * 2 * HW_ + HW_ + hwn];
    float4 ng7 = g_pc4[(size_t)b * 8 * HW_ + 7 * HW_ + hwn];
    float n0x1 = ng0.x, n1x1 = ng0.y, n0y1 = ng0.z, n1y1 = ng0.w;
    float n0x2 = ng1.x, n1x2 = ng1.y, n0y2 = ng1.z, n1y2 = ng1.w;
    float an0 = ng7.z, an1 = ng7.w;

    ull p0p[5];
#pragma unroll
    for (int k = 0; k < 5; k++) {
        float2 t = g_p0f2[((size_t)b * 5 + k) * HW_ + hwn];
        p0p[k] = pk(t.x, t.y);
    }

    ull acc0p[5], acc1p[5], sm0p[5], sm1p[5];
#pragma unroll
    for (int k = 0; k < 5; k++) { acc0p[k] = 0; acc1p[k] = 0; sm0p[k] = 0; sm1p[k] = 0; }

    const float4* gb = g_bev4 + (size_t)b * 2 * HW_ + h * 512;
    const float4* gp = g_pc4 + (size_t)b * 8 * HW_ + h * 512;

    // prefetch tile 0
    {
        uint32_t sba = (uint32_t)__cvta_generic_to_shared(&sb[0][0]);
        uint32_t spa = (uint32_t)__cvta_generic_to_shared(&sp[0][0]);
#pragma unroll
        for (int g = 0; g < 2; g++)
            cpasync16(sba + (g * TILE + tid) * 16, gb + g * HW_ + tid);
#pragma unroll
        for (int g = 0; g < 8; g++)
            cpasync16(spa + (g * TILE + tid) * 16, gp + g * HW_ + tid);
        asm volatile("cp.async.commit_group;");
    }

    for (int t = 0; t < 4; t++) {
        if (t < 3) {
            int nb = (t + 1) & 1;
            uint32_t sba = (uint32_t)__cvta_generic_to_shared(&sb[nb][0]);
            uint32_t spa = (uint32_t)__cvta_generic_to_shared(&sp[nb][0]);
            int off = (t + 1) * TILE + tid;
#pragma unroll
            for (int g = 0; g < 2; g++)
                cpasync16(sba + (g * TILE + tid) * 16, gb + g * HW_ + off);
#pragma unroll
            for (int g = 0; g < 8; g++)
                cpasync16(spa + (g * TILE + tid) * 16, gp + g * HW_ + off);
            asm volatile("cp.async.commit_group;");
            asm volatile("cp.async.wait_group 1;");
        } else {
            asm volatile("cp.async.wait_group 0;");
        }
        __syncthreads();

        const float4*     SB = sb[t & 1];
        const ulonglong2* SP = sp[t & 1];
#pragma unroll 2
        for (int j = 0; j < 4; j++) {
            int m = lane + j * 32;
            float4 bg0 = SB[m];
            float4 bg1 = SB[TILE + m];
            float4 G7f = ((const float4*)SP)[7 * TILE + m];

            float q00 = iou1(n0x1, n0y1, n0x2, n0y2, an0, bg0.x, bg0.z, bg1.x, bg1.z, G7f.z);
            float q01 = iou1(n0x1, n0y1, n0x2, n0y2, an0, bg0.y, bg0.w, bg1.y, bg1.w, G7f.w);
            float q10 = iou1(n1x1, n1y1, n1x2, n1y2, an1, bg0.x, bg0.z, bg1.x, bg1.z, G7f.z);
            float q11 = iou1(n1x1, n1y1, n1x2, n1y2, an1, bg0.y, bg0.w, bg1.y, bg1.w, G7f.w);

            float e00 = ex2(q00), e01 = ex2(q01);
            float e10 = ex2(q10), e11 = ex2(q11);
            ull e00s = pk(e00, e00), e01s = pk(e01, e01);
            ull e10s = pk(e10, e10), e11s = pk(e11, e11);
            ull es0s = pk(e00 + e01, e00 + e01);
            ull es1s = pk(e10 + e11, e10 + e11);

            ulonglong2 G5 = SP[5 * TILE + m];
            ulonglong2 G6 = SP[6 * TILE + m];
            ull p1p[5] = { G5.x, G5.y, G6.x, G6.y, pk(G7f.x, G7f.y) };

#pragma unroll
            for (int k = 0; k < 5; k++) {
                ull tt = mul2(p0p[k], p1p[k]);
                float b0, b1; upk(tt, b0, b1);
                ull ebp = pk(ex2(b0), ex2(b1));

                ulonglong2 Wk = SP[k * TILE + m];
                ull s0p = fma2(e01s, Wk.y, mul2(e00s, Wk.x));
                ull s1p = fma2(e11s, Wk.y, mul2(e10s, Wk.x));
                acc0p[k] = fma2(ebp, s0p, acc0p[k]);
                acc1p[k] = fma2(ebp, s1p, acc1p[k]);
                sm0p[k]  = fma2(ebp, es0s, sm0p[k]);
                sm1p[k]  = fma2(ebp, es1s, sm1p[k]);
            }
        }
        __syncthreads();
    }

    // warp butterfly reduction
#pragma unroll
    for (int o = 16; o > 0; o >>= 1) {
#pragma unroll
        for (int k = 0; k < 5; k++) {
            acc0p[k] = add2(acc0p[k], __shfl_xor_sync(0xffffffffu, acc0p[k], o));
            acc1p[k] = add2(acc1p[k], __shfl_xor_sync(0xffffffffu, acc1p[k], o));
            sm0p[k]  = add2(sm0p[k],  __shfl_xor_sync(0xffffffffu, sm0p[k],  o));
            sm1p[k]  = add2(sm1p[k],  __shfl_xor_sync(0xffffffffu, sm1p[k],  o));
        }
    }

    if (lane == 0) {
        ull* P = g_part + ((size_t)(h * NBOX + gw) * 5) * 4;
#pragma unroll
        for (int k = 0; k < 5; k++) {
            P[k * 4 + 0] = acc0p[k];
            P[k * 4 + 1] = acc1p[k];
            P[k * 4 + 2] = sm0p[k];
            P[k * 4 + 3] = sm1p[k];
        }
    }
    __syncthreads();

    // ---- combine: second arriver of this quad merges both halves ----
    if (tid == 0) {
        __threadfence();
        s_old = atomicAdd(&g_qctr[q], 1u);
    }
    __syncthreads();

    if (s_old == 1u) {
        if (tid == 0) {
            while (ld_acq(&g_ctr[1]) < N_SCS) __nanosleep(64);
        }
        __syncthreads();
        if (tid < 20) {
            int w = tid / 5;
            int k = tid - w * 5;
            int cell = q * 4 + w;
            int cb2 = cell >> 10;
            int hw2 = cell & (HW_ - 1);
            const ull* P0 = g_part + ((size_t)cell * 5 + k) * 4;
            const ull* P1 = P0 + (size_t)NBOX * 5 * 4;
            ull a0 = add2(P0[0], P1[0]);
            ull a1 = add2(P0[1], P1[1]);
            ull s0 = add2(P0[2], P1[2]);
            ull s1 = add2(P0[3], P1[3]);
            int c0 = 2 * k, c1 = 2 * k + 1;
            float i0 = g_scinv[cb2 * C_ + c0];
            float i1 = g_scinv[cb2 * C_ + c1];
            float v0, v1, d0, d1;
            upk(a0, v0, v1); upk(s0, d0, d1);
            out[((cb2 * A_ + 0) * C_ + c0) * HW_ + hw2] = v0 * rcpf(d0) * i0;
            out[((cb2 * A_ + 0) * C_ + c1) * HW_ + hw2] = v1 * rcpf(d1) * i1;
            upk(a1, v0, v1); upk(s1, d0, d1);
            out[((cb2 * A_ + 1) * C_ + c0) * HW_ + hw2] = v0 * rcpf(d0) * i0;
            out[((cb2 * A_ + 1) * C_ + c1) * HW_ + hw2] = v1 * rcpf(d1) * i1;
        }
        __syncthreads();
        if (tid == 0) g_qctr[q] = 0u;   // self-reset for next launch
    }

    // last compute block resets global counters for the next launch
    if (tid == 0) {
        __threadfence();
        unsigned f = atomicAdd(&g_ctr[2], 1u);
        if (f == N_COMP - 1u) {
            g_ctr[0] = 0u;
            g_ctr[1] = 0u;
            g_ctr[2] = 0u;
        }
    }
}

extern "C" void kernel_launch(void* const* d_in, const int* in_sizes, int n_in,
                              void* d_out, int out_size) {
    const float* scores = (const float*)d_in[0];
    const float* bbox = (const float*)d_in[1];
    const float* pp = (const float*)d_in[2];
    const float* dec = (const float*)d_in[3];
    float* out = (float*)d_out;

    k_all<<<B_TOTAL, 128>>>(scores, bbox, pp, dec, out);
}

// round 16
// speedup vs baseline: 1.0083x; 1.0083x over previous
#include <cuda_runtime.h>
#include <cstdint>

// Problem constants
#define BATCH 2
#define A_    2
#define C_    10
#define HW_   1024
#define NBOX  2048
#define TILE  128
#define LOG2E 1.4426950408889634f
#define PI_F  3.14159265358979323846f

// Output layout: out_scores [0,40960) | bbox [40960,69632) | pp [69632,131072)
#define OUT_BBOX 40960
#define OUT_PP   69632

// Block ranges in the single kernel
#define B_WPACK  80     // [0,80)    wpack
#define B_P1PACK 112    // [80,112)  p1pack
#define B_P1TAIL 128    // [112,128) p1tail
#define B_P0PACK 208    // [128,208) p0pack
#define B_BEV    224    // [208,224) bev
#define B_SCSUM  244    // [224,244) scsum
#define B_COPY   332    // [244,332) copies
#define B_TOTAL  1356   // [332,1356) compute (1024)
#define N_PREP   224u
#define N_SCS    20u
#define N_COMP   1024u

// ---------------- scratch tables (SoA-group layouts) ----------------
__device__ __align__(16) float4 g_bev4[BATCH * 2 * HW_];
__device__ __align__(16) float4 g_pc4[BATCH * 8 * HW_];
__device__ __align__(8)  float2 g_p0f2[BATCH * 5 * HW_];
__device__ float g_scinv[BATCH * C_];

typedef unsigned long long ull;
// partial sums: [h][cell][k][{acc0,acc1,sm0,sm1}]
__device__ __align__(16) ull g_part[2 * NBOX * 5 * 4];
// counters (zero-initialized; self-resetting every launch)
__device__ unsigned g_ctr[3];        // [0]=prep done, [1]=scsum done, [2]=compute finished
__device__ unsigned g_qctr[512];     // per n-quad arrivals (self-reset by combiner)

// ---------------- helpers ----------------
__device__ __forceinline__ float ex2(float x) {
    float y; asm("ex2.approx.f32 %0, %1;" : "=f"(y) : "f"(x)); return y;
}
__device__ __forceinline__ float rcpf(float x) {
    float y; asm("rcp.approx.f32 %0, %1;" : "=f"(y) : "f"(x)); return y;
}
__device__ __forceinline__ ull pk(float a, float b) {
    ull r; asm("mov.b64 %0, {%1,%2};" : "=l"(r) : "f"(a), "f"(b)); return r;
}
__device__ __forceinline__ void upk(ull v, float& a, float& b) {
    asm("mov.b64 {%0,%1}, %2;" : "=f"(a), "=f"(b) : "l"(v));
}
__device__ __forceinline__ ull mul2(ull a, ull b) {
    ull r; asm("mul.rn.f32x2 %0, %1, %2;" : "=l"(r) : "l"(a), "l"(b)); return r;
}
__device__ __forceinline__ ull fma2(ull a, ull b, ull c) {
    ull r; asm("fma.rn.f32x2 %0, %1, %2, %3;" : "=l"(r) : "l"(a), "l"(b), "l"(c)); return r;
}
__device__ __forceinline__ ull add2(ull a, ull b) {
    ull r; asm("add.rn.f32x2 %0, %1, %2;" : "=l"(r) : "l"(a), "l"(b)); return r;
}
__device__ __forceinline__ void cpasync16(uint32_t saddr, const void* g) {
    asm volatile("cp.async.cg.shared.global [%0], [%1], 16;" :: "r"(saddr), "l"(g));
}
__device__ __forceinline__ unsigned ld_acq(const unsigned* p) {
    unsigned v;
    asm volatile("ld.acquire.gpu.global.u32 %0, [%1];" : "=r"(v) : "l"(p) : "memory");
    return v;
}

__device__ __forceinline__ float iou1(float ax1, float ay1, float ax2, float ay2, float aa,
                                      float bx1, float by1, float bx2, float by2, float ba) {
    float ltx = fmaxf(ax1, bx1);
    float lty = fmaxf(ay1, by1);
    float rbx = fminf(ax2, bx2);
    float rby = fminf(ay2, by2);
    float w = fmaxf(rbx - ltx, 0.f);
    float h = fmaxf(rby - lty, 0.f);
    float inter = w * h;
    float uni = fmaxf(aa + ba - inter, 1e-6f);
    return inter * LOG2E * rcpf(uni);
}

// ---------------------------------------------------------------------------
// THE kernel: prep + scsum + copies + compute + combine, one launch.
// ---------------------------------------------------------------------------
__global__ void __launch_bounds__(128, 5) k_all(
        const float* __restrict__ scores,
        const float* __restrict__ bbox,
        const float* __restrict__ pp,
        const float* __restrict__ dec,
        float* __restrict__ out) {
    int blk = blockIdx.x;
    int tid = threadIdx.x;

    if (blk < B_BEV) {
        // ============ prep slices ============
        if (blk < B_WPACK) {
            int i = blk * 128 + tid;          // [0, 10240)
            int b = i / 5120;
            int r = i - b * 5120;
            int k = r >> 10;
            int hw = r & (HW_ - 1);
            int c0 = 2 * k, c1 = 2 * k + 1;
            const float* sb = scores + (size_t)b * 2 * C_ * HW_ + hw;
            float e00 = __expf(sb[(0 * C_ + c0) * HW_]);
            float e10 = __expf(sb[(0 * C_ + c1) * HW_]);
            float e01 = __expf(sb[(1 * C_ + c0) * HW_]);
            float e11 = __expf(sb[(1 * C_ + c1) * HW_]);
            g_pc4[((size_t)b * 8 + k) * HW_ + hw] = make_float4(e00, e10, e01, e11);
        } else if (blk < B_P1PACK) {
            int i = (blk - B_WPACK) * 128 + tid;  // [0, 4096)
            int b = i >> 11;
            int r = i & 2047;
            int g5 = r >> 10;
            int hw = r & (HW_ - 1);
            int cb = 4 * g5;
            const float* pb = pp + (size_t)b * 30 * HW_ + hw;
            float4 v = make_float4(pb[(3 * (cb + 0) + 1) * HW_],
                                   pb[(3 * (cb + 1) + 1) * HW_],
                                   pb[(3 * (cb + 2) + 1) * HW_],
                                   pb[(3 * (cb + 3) + 1) * HW_]);
            g_pc4[((size_t)b * 8 + 5 + g5) * HW_ + hw] = v;
        } else if (blk < B_P1TAIL) {
            int i = (blk - B_P1PACK) * 128 + tid; // [0, 2048)
            int b = i >> 10;
            int hw = i & (HW_ - 1);
            const float* pb = pp + (size_t)b * 30 * HW_ + hw;
            float2 v = make_float2(pb[25 * HW_], pb[28 * HW_]);
            *(float2*)&g_pc4[((size_t)b * 8 + 7) * HW_ + hw].x = v;
        } else if (blk < B_P0PACK) {
            int i = (blk - B_P1TAIL) * 128 + tid; // [0, 10240)
            int b = i / 5120;
            int r = i - b * 5120;
            int k = r >> 10;
            int hw = r & (HW_ - 1);
            const float* pb = pp + (size_t)b * 30 * HW_ + hw;
            float2 v = make_float2(pb[(3 * (2 * k)) * HW_] * LOG2E,
                                   pb[(3 * (2 * k + 1)) * HW_] * LOG2E);
            g_p0f2[((size_t)b * 5 + k) * HW_ + hw] = v;
        } else {
            int i = (blk - B_P0PACK) * 128 + tid; // [0, 2048)
            int b = i >> 10;
            int hw = i & (HW_ - 1);
            float x1a[2], y1a[2], x2a[2], y2a[2], area[2];
#pragma unroll
            for (int a = 0; a < 2; a++) {
                const float* d7 = dec + ((size_t)b * NBOX + hw * 2 + a) * 7;
                float x = d7[0], y = d7[1], dx = d7[3], dy = d7[4], yaw = d7[6];
                float normed = fabsf(yaw - floorf(yaw / PI_F + 0.5f) * PI_F);
                bool sw = normed > 0.25f * PI_F;
                float w = sw ? dy : dx;
                float h = sw ? dx : dy;
                x1a[a] = x - 0.5f * w; y1a[a] = y - 0.5f * h;
                x2a[a] = x + 0.5f * w; y2a[a] = y + 0.5f * h;
                area[a] = (x2a[a] - x1a[a]) * (y2a[a] - y1a[a]);
            }
            float4* bv = g_bev4 + (size_t)b * 2 * HW_ + hw;
            bv[0]   = make_float4(x1a[0], x1a[1], y1a[0], y1a[1]);
            bv[HW_] = make_float4(x2a[0], x2a[1], y2a[0], y2a[1]);
            *(float2*)&g_pc4[((size_t)b * 8 + 7) * HW_ + hw].z = make_float2(area[0], area[1]);
        }
        __syncthreads();
        if (tid == 0) {
            __threadfence();
            atomicAdd(&g_ctr[0], 1u);
        }
        return;
    }

    if (blk < B_SCSUM) {
        // ============ score-softmax denominators ============
        int s = blk - B_BEV;
        int b = s / C_, c = s % C_;
        __shared__ float red[128];
        float acc = 0.f;
        for (int m = tid; m < NBOX; m += 128) {
            int a = m & 1, hw = m >> 1;
            acc += __expf(scores[((b * A_ + a) * C_ + c) * HW_ + hw]);
        }
        red[tid] = acc;
        __syncthreads();
#pragma unroll
        for (int o = 64; o > 0; o >>= 1) {
            if (tid < o) red[tid] += red[tid + o];
            __syncthreads();
        }
        if (tid == 0) {
            g_scinv[b * C_ + c] = 1.0f / red[0];
            __threadfence();
            atomicAdd(&g_ctr[1], 1u);
        }
        return;
    }

    if (blk < B_COPY) {
        // ============ pass-through copies ============
        int base = (blk - B_SCSUM) * 128 + tid;   // [0, 11264)
#pragma unroll
        for (int r = 0; r < 2; r++) {
            int i = base + r * 11264;
            if (i < 7168)
                ((float4*)(out + OUT_BBOX))[i] = ((const float4*)bbox)[i];
            else
                ((float4*)(out + OUT_PP))[i - 7168] = ((const float4*)pp)[i - 7168];
        }
        return;
    }

    // ============ compute: (n-quad, m-half) ============
    __shared__ __align__(16) float4     sb[2][2 * TILE];
    __shared__ __align__(16) ulonglong2 sp[2][8 * TILE];
    __shared__ unsigned s_old;

    // wait for prep
    if (tid == 0) {
        while (ld_acq(&g_ctr[0]) < N_PREP) __nanosleep(64);
    }
    __syncthreads();

    int lane = tid & 31;
    int cb = blk - B_COPY;
    int h = cb & 1;
    int q = cb >> 1;                       // n-quad [0,512)
    int gw = q * 4 + (tid >> 5);           // n-cell [0,2048)
    int b = gw >> 10;
    int hwn = gw & (HW_ - 1);

    float4 ng0 = g_bev4[(size_t)b * 2 * HW_ + hwn];
    float4 ng1 = g_bev4[(size_t)b * 2 * HW_ + HW_ + hwn];
    float4 ng7 = g_pc4[(size_t)b * 8 * HW_ + 7 * HW_ + hwn];
    float n0x1 = ng0.x, n1x1 = ng0.y, n0y1 = ng0.z, n1y1 = ng0.w;
    float n0x2 = ng1.x, n1x2 = ng1.y, n0y2 = ng1.z, n1y2 = ng1.w;
    float an0 = ng7.z, an1 = ng7.w;

    ull p0p[5];
#pragma unroll
    for (int k = 0; k < 5; k++) {
        float2 t = g_p0f2[((size_t)b * 5 + k) * HW_ + hwn];
        p0p[k] = pk(t.x, t.y);
    }

    ull acc0p[5], acc1p[5], sm0p[5], sm1p[5];
#pragma unroll
    for (int k = 0; k < 5; k++) { acc0p[k] = 0; acc1p[k] = 0; sm0p[k] = 0; sm1p[k] = 0; }

    const float4* gb = g_bev4 + (size_t)b * 2 * HW_ + h * 512;
    const float4* gp = g_pc4 + (size_t)b * 8 * HW_ + h * 512;

    // prefetch tile 0
    {
        uint32_t sba = (uint32_t)__cvta_generic_to_shared(&sb[0][0]);
        uint32_t spa = (uint32_t)__cvta_generic_to_shared(&sp[0][0]);
#pragma unroll
        for (int g = 0; g < 2; g++)
            cpasync16(sba + (g * TILE + tid) * 16, gb + g * HW_ + tid);
#pragma unroll
        for (int g = 0; g < 8; g++)
            cpasync16(spa + (g * TILE + tid) * 16, gp + g * HW_ + tid);
        asm volatile("cp.async.commit_group;");
    }

    for (int t = 0; t < 4; t++) {
        if (t < 3) {
            int nb = (t + 1) & 1;
            uint32_t sba = (uint32_t)__cvta_generic_to_shared(&sb[nb][0]);
            uint32_t spa = (uint32_t)__cvta_generic_to_shared(&sp[nb][0]);
            int off = (t + 1) * TILE + tid;
#pragma unroll
            for (int g = 0; g < 2; g++)
                cpasync16(sba + (g * TILE + tid) * 16, gb + g * HW_ + off);
#pragma unroll
            for (int g = 0; g < 8; g++)
                cpasync16(spa + (g * TILE + tid) * 16, gp + g * HW_ + off);
            asm volatile("cp.async.commit_group;");
            asm volatile("cp.async.wait_group 1;");
        } else {
            asm volatile("cp.async.wait_group 0;");
        }
        __syncthreads();

        const float4*     SB = sb[t & 1];
        const ulonglong2* SP = sp[t & 1];
#pragma unroll 2
        for (int j = 0; j < 4; j++) {
            int m = lane + j * 32;
            float4 bg0 = SB[m];
            float4 bg1 = SB[TILE + m];
            float4 G7f = ((const float4*)SP)[7 * TILE + m];

            float q00 = iou1(n0x1, n0y1, n0x2, n0y2, an0, bg0.x, bg0.z, bg1.x, bg1.z, G7f.z);
            float q01 = iou1(n0x1, n0y1, n0x2, n0y2, an0, bg0.y, bg0.w, bg1.y, bg1.w, G7f.w);
            float q10 = iou1(n1x1, n1y1, n1x2, n1y2, an1, bg0.x, bg0.z, bg1.x, bg1.z, G7f.z);
            float q11 = iou1(n1x1, n1y1, n1x2, n1y2, an1, bg0.y, bg0.w, bg1.y, bg1.w, G7f.w);

            float e00 = ex2(q00), e01 = ex2(q01);
            float e10 = ex2(q10), e11 = ex2(q11);
            ull e00s = pk(e00, e00), e01s = pk(e01, e01);
            ull e10s = pk(e10, e10), e11s = pk(e11, e11);
            ull es0s = pk(e00 + e01, e00 + e01);
            ull es1s = pk(e10 + e11, e10 + e11);

            ulonglong2 G5 = SP[5 * TILE + m];
            ulonglong2 G6 = SP[6 * TILE + m];
            ull p1p[5] = { G5.x, G5.y, G6.x, G6.y, pk(G7f.x, G7f.y) };

#pragma unroll
            for (int k = 0; k < 5; k++) {
                ull tt = mul2(p0p[k], p1p[k]);
                float b0, b1; upk(tt, b0, b1);
                ull ebp = pk(ex2(b0), ex2(b1));

                ulonglong2 Wk = SP[k * TILE + m];
                ull s0p = fma2(e01s, Wk.y, mul2(e00s, Wk.x));
                ull s1p = fma2(e11s, Wk.y, mul2(e10s, Wk.x));
                acc0p[k] = fma2(ebp, s0p, acc0p[k]);
                acc1p[k] = fma2(ebp, s1p, acc1p[k]);
                sm0p[k]  = fma2(ebp, es0s, sm0p[k]);
                sm1p[k]  = fma2(ebp, es1s, sm1p[k]);
            }
        }
        __syncthreads();
    }

    // warp butterfly reduction
#pragma unroll
    for (int o = 16; o > 0; o >>= 1) {
#pragma unroll
        for (int k = 0; k < 5; k++) {
            acc0p[k] = add2(acc0p[k], __shfl_xor_sync(0xffffffffu, acc0p[k], o));
            acc1p[k] = add2(acc1p[k], __shfl_xor_sync(0xffffffffu, acc1p[k], o));
            sm0p[k]  = add2(sm0p[k],  __shfl_xor_sync(0xffffffffu, sm0p[k],  o));
            sm1p[k]  = add2(sm1p[k],  __shfl_xor_sync(0xffffffffu, sm1p[k],  o));
        }
    }

    if (lane == 0) {
        ull* P = g_part + ((size_t)(h * NBOX + gw) * 5) * 4;
#pragma unroll
        for (int k = 0; k < 5; k++) {
            P[k * 4 + 0] = acc0p[k];
            P[k * 4 + 1] = acc1p[k];
            P[k * 4 + 2] = sm0p[k];
            P[k * 4 + 3] = sm1p[k];
        }
    }
    __syncthreads();

    // ---- combine: second arriver of this quad merges both halves ----
    if (tid == 0) {
        __threadfence();
        s_old = atomicAdd(&g_qctr[q], 1u);
    }
    __syncthreads();

    if (s_old == 1u) {
        if (tid == 0) {
            while (ld_acq(&g_ctr[1]) < N_SCS) __nanosleep(64);
        }
        __syncthreads();
        if (tid < 20) {
            int w = tid / 5;
            int k = tid - w * 5;
            int cell = q * 4 + w;
            int cb2 = cell >> 10;
            int hw2 = cell & (HW_ - 1);
            const ull* P0 = g_part + ((size_t)cell * 5 + k) * 4;
            const ull* P1 = P0 + (size_t)NBOX * 5 * 4;
            ull a0 = add2(P0[0], P1[0]);
            ull a1 = add2(P0[1], P1[1]);
            ull s0 = add2(P0[2], P1[2]);
            ull s1 = add2(P0[3], P1[3]);
            int c0 = 2 * k, c1 = 2 * k + 1;
            float i0 = g_scinv[cb2 * C_ + c0];
            float i1 = g_scinv[cb2 * C_ + c1];
            float v0, v1, d0, d1;
            upk(a0, v0, v1); upk(s0, d0, d1);
            out[((cb2 * A_ + 0) * C_ + c0) * HW_ + hw2] = v0 * rcpf(d0) * i0;
            out[((cb2 * A_ + 0) * C_ + c1) * HW_ + hw2] = v1 * rcpf(d1) * i1;
            upk(a1, v0, v1); upk(s1, d0, d1);
            out[((cb2 * A_ + 1) * C_ + c0) * HW_ + hw2] = v0 * rcpf(d0) * i0;
            out[((cb2 * A_ + 1) * C_ + c1) * HW_ + hw2] = v1 * rcpf(d1) * i1;
        }
        __syncthreads();
        if (tid == 0) g_qctr[q] = 0u;   // self-reset for next launch
    }

    // last compute block resets global counters for the next launch
    if (tid == 0) {
        __threadfence();
        unsigned f = atomicAdd(&g_ctr[2], 1u);
        if (f == N_COMP - 1u) {
            g_ctr[0] = 0u;
            g_ctr[1] = 0u;
            g_ctr[2] = 0u;
        }
    }
}

extern "C" void kernel_launch(void* const* d_in, const int* in_sizes, int n_in,
                              void* d_out, int out_size) {
    const float* scores = (const float*)d_in[0];
    const float* bbox = (const float*)d_in[1];
    const float* pp = (const float*)d_in[2];
    const float* dec = (const float*)d_in[3];
    float* out = (float*)d_out;

    k_all<<<B_TOTAL, 128>>>(scores, bbox, pp, dec, out);
}

// round 17
// speedup vs baseline: 1.0517x; 1.0431x over previous
#include <cuda_runtime.h>
#include <cstdint>

// Problem constants
#define BATCH 2
#define A_    2
#define C_    10
#define HW_   1024
#define NBOX  2048
#define TILE  128
#define LOG2E 1.4426950408889634f
#define PI_F  3.14159265358979323846f

// Output layout: out_scores [0,40960) | bbox [40960,69632) | pp [69632,131072)
#define OUT_BBOX 40960
#define OUT_PP   69632

// L1 prep block ranges (224 blocks x 128 threads)
#define B_WPACK  80     // [0,80)    wpack
#define B_P1PACK 112    // [80,112)  p1pack
#define B_P1TAIL 128    // [112,128) p1tail
#define B_P0PACK 208    // [128,208) p0pack
#define B_BEV    224    // [208,224) bev

// L2 block ranges
#define L2_SCS   20     // [0,20)    scsum
#define L2_COPY  108    // [20,108)  copies
#define L2_TOTAL 1132   // [108,1132) compute (1024)
#define N_SCS    20u
#define N_COMP   1024u

// ---------------- scratch tables (SoA-group layouts) ----------------
__device__ __align__(16) float4 g_bev4[BATCH * 2 * HW_];
__device__ __align__(16) float4 g_pc4[BATCH * 8 * HW_];
__device__ __align__(8)  float2 g_p0f2[BATCH * 5 * HW_];
__device__ float g_scinv[BATCH * C_];

typedef unsigned long long ull;
// partial sums: [h][cell][k][{acc0,acc1,sm0,sm1}]
__device__ __align__(16) ull g_part[2 * NBOX * 5 * 4];
// counters (zero-initialized; self-resetting every launch)
__device__ unsigned g_ctr[3];        // [1]=scsum done, [2]=compute finished
__device__ unsigned g_qctr[512];     // per n-quad arrivals (self-reset by combiner)

// ---------------- helpers ----------------
__device__ __forceinline__ float ex2(float x) {
    float y; asm("ex2.approx.f32 %0, %1;" : "=f"(y) : "f"(x)); return y;
}
__device__ __forceinline__ float rcpf(float x) {
    float y; asm("rcp.approx.f32 %0, %1;" : "=f"(y) : "f"(x)); return y;
}
__device__ __forceinline__ ull pk(float a, float b) {
    ull r; asm("mov.b64 %0, {%1,%2};" : "=l"(r) : "f"(a), "f"(b)); return r;
}
__device__ __forceinline__ void upk(ull v, float& a, float& b) {
    asm("mov.b64 {%0,%1}, %2;" : "=f"(a), "=f"(b) : "l"(v));
}
__device__ __forceinline__ ull mul2(ull a, ull b) {
    ull r; asm("mul.rn.f32x2 %0, %1, %2;" : "=l"(r) : "l"(a), "l"(b)); return r;
}
__device__ __forceinline__ ull fma2(ull a, ull b, ull c) {
    ull r; asm("fma.rn.f32x2 %0, %1, %2, %3;" : "=l"(r) : "l"(a), "l"(b), "l"(c)); return r;
}
__device__ __forceinline__ ull add2(ull a, ull b) {
    ull r; asm("add.rn.f32x2 %0, %1, %2;" : "=l"(r) : "l"(a), "l"(b)); return r;
}
__device__ __forceinline__ void cpasync16(uint32_t saddr, const void* g) {
    asm volatile("cp.async.cg.shared.global [%0], [%1], 16;" :: "r"(saddr), "l"(g));
}
__device__ __forceinline__ unsigned ld_acq(const unsigned* p) {
    unsigned v;
    asm volatile("ld.acquire.gpu.global.u32 %0, [%1];" : "=r"(v) : "l"(p) : "memory");
    return v;
}

__device__ __forceinline__ float iou1(float ax1, float ay1, float ax2, float ay2, float aa,
                                      float bx1, float by1, float bx2, float by2, float ba) {
    float ltx = fmaxf(ax1, bx1);
    float lty = fmaxf(ay1, by1);
    float rbx = fminf(ax2, bx2);
    float rby = fminf(ay2, by2);
    float w = fmaxf(rbx - ltx, 0.f);
    float h = fmaxf(rby - lty, 0.f);
    float inter = w * h;
    float uni = fmaxf(aa + ba - inter, 1e-6f);
    return inter * LOG2E * rcpf(uni);
}

// ---------------------------------------------------------------------------
// L1: prep — wide, coalesced, elementwise slices only.
// ---------------------------------------------------------------------------
__global__ void k_prep(const float* __restrict__ scores,
                       const float* __restrict__ pp,
                       const float* __restrict__ dec) {
    int blk = blockIdx.x;
    int tid = threadIdx.x;

    if (blk < B_WPACK) {
        int i = blk * 128 + tid;          // [0, 10240)
        int b = i / 5120;
        int r = i - b * 5120;
        int k = r >> 10;
        int hw = r & (HW_ - 1);
        int c0 = 2 * k, c1 = 2 * k + 1;
        const float* sb = scores + (size_t)b * 2 * C_ * HW_ + hw;
        float e00 = __expf(sb[(0 * C_ + c0) * HW_]);
        float e10 = __expf(sb[(0 * C_ + c1) * HW_]);
        float e01 = __expf(sb[(1 * C_ + c0) * HW_]);
        float e11 = __expf(sb[(1 * C_ + c1) * HW_]);
        g_pc4[((size_t)b * 8 + k) * HW_ + hw] = make_float4(e00, e10, e01, e11);
    } else if (blk < B_P1PACK) {
        int i = (blk - B_WPACK) * 128 + tid;  // [0, 4096)
        int b = i >> 11;
        int r = i & 2047;
        int g5 = r >> 10;
        int hw = r & (HW_ - 1);
        int cb = 4 * g5;
        const float* pb = pp + (size_t)b * 30 * HW_ + hw;
        float4 v = make_float4(pb[(3 * (cb + 0) + 1) * HW_],
                               pb[(3 * (cb + 1) + 1) * HW_],
                               pb[(3 * (cb + 2) + 1) * HW_],
                               pb[(3 * (cb + 3) + 1) * HW_]);
        g_pc4[((size_t)b * 8 + 5 + g5) * HW_ + hw] = v;
    } else if (blk < B_P1TAIL) {
        int i = (blk - B_P1PACK) * 128 + tid; // [0, 2048)
        int b = i >> 10;
        int hw = i & (HW_ - 1);
        const float* pb = pp + (size_t)b * 30 * HW_ + hw;
        float2 v = make_float2(pb[25 * HW_], pb[28 * HW_]);
        *(float2*)&g_pc4[((size_t)b * 8 + 7) * HW_ + hw].x = v;
    } else if (blk < B_P0PACK) {
        int i = (blk - B_P1TAIL) * 128 + tid; // [0, 10240)
        int b = i / 5120;
        int r = i - b * 5120;
        int k = r >> 10;
        int hw = r & (HW_ - 1);
        const float* pb = pp + (size_t)b * 30 * HW_ + hw;
        float2 v = make_float2(pb[(3 * (2 * k)) * HW_] * LOG2E,
                               pb[(3 * (2 * k + 1)) * HW_] * LOG2E);
        g_p0f2[((size_t)b * 5 + k) * HW_ + hw] = v;
    } else {
        int i = (blk - B_P0PACK) * 128 + tid; // [0, 2048)
        int b = i >> 10;
        int hw = i & (HW_ - 1);
        float x1a[2], y1a[2], x2a[2], y2a[2], area[2];
#pragma unroll
        for (int a = 0; a < 2; a++) {
            const float* d7 = dec + ((size_t)b * NBOX + hw * 2 + a) * 7;
            float x = d7[0], y = d7[1], dx = d7[3], dy = d7[4], yaw = d7[6];
            float normed = fabsf(yaw - floorf(yaw / PI_F + 0.5f) * PI_F);
            bool sw = normed > 0.25f * PI_F;
            float w = sw ? dy : dx;
            float h = sw ? dx : dy;
            x1a[a] = x - 0.5f * w; y1a[a] = y - 0.5f * h;
            x2a[a] = x + 0.5f * w; y2a[a] = y + 0.5f * h;
            area[a] = (x2a[a] - x1a[a]) * (y2a[a] - y1a[a]);
        }
        float4* bv = g_bev4 + (size_t)b * 2 * HW_ + hw;
        bv[0]   = make_float4(x1a[0], x1a[1], y1a[0], y1a[1]);
        bv[HW_] = make_float4(x2a[0], x2a[1], y2a[0], y2a[1]);
        *(float2*)&g_pc4[((size_t)b * 8 + 7) * HW_ + hw].z = make_float2(area[0], area[1]);
    }
}

// ---------------------------------------------------------------------------
// L2: scsum [0,20) + copies [20,108) + compute/combine [108,1132).
//     No entry spin: prep finished in the previous launch.
// ---------------------------------------------------------------------------
__global__ void __launch_bounds__(128, 5) k_main(
        const float* __restrict__ scores,
        const float* __restrict__ bbox,
        const float* __restrict__ pp,
        float* __restrict__ out) {
    int blk = blockIdx.x;
    int tid = threadIdx.x;

    if (blk < L2_SCS) {
        // ============ score-softmax denominators ============
        int b = blk / C_, c = blk % C_;
        __shared__ float red[128];
        float acc = 0.f;
        for (int m = tid; m < NBOX; m += 128) {
            int a = m & 1, hw = m >> 1;
            acc += __expf(scores[((b * A_ + a) * C_ + c) * HW_ + hw]);
        }
        red[tid] = acc;
        __syncthreads();
#pragma unroll
        for (int o = 64; o > 0; o >>= 1) {
            if (tid < o) red[tid] += red[tid + o];
            __syncthreads();
        }
        if (tid == 0) {
            g_scinv[b * C_ + c] = 1.0f / red[0];
            __threadfence();
            atomicAdd(&g_ctr[1], 1u);
        }
        return;
    }

    if (blk < L2_COPY) {
        // ============ pass-through copies: 88 blocks * 128 thr * 2 f4 ============
        int base = (blk - L2_SCS) * 128 + tid;   // [0, 11264)
#pragma unroll
        for (int r = 0; r < 2; r++) {
            int i = base + r * 11264;
            if (i < 7168)
                ((float4*)(out + OUT_BBOX))[i] = ((const float4*)bbox)[i];
            else
                ((float4*)(out + OUT_PP))[i - 7168] = ((const float4*)pp)[i - 7168];
        }
        return;
    }

    // ============ compute: (n-quad, m-half) ============
    __shared__ __align__(16) float4     sb[2][2 * TILE];
    __shared__ __align__(16) ulonglong2 sp[2][8 * TILE];
    __shared__ unsigned s_old;

    int lane = tid & 31;
    int cb = blk - L2_COPY;
    int h = cb & 1;
    int q = cb >> 1;                       // n-quad [0,512)
    int gw = q * 4 + (tid >> 5);           // n-cell [0,2048)
    int b = gw >> 10;
    int hwn = gw & (HW_ - 1);

    float4 ng0 = g_bev4[(size_t)b * 2 * HW_ + hwn];
    float4 ng1 = g_bev4[(size_t)b * 2 * HW_ + HW_ + hwn];
    float4 ng7 = g_pc4[(size_t)b * 8 * HW_ + 7 * HW_ + hwn];
    float n0x1 = ng0.x, n1x1 = ng0.y, n0y1 = ng0.z, n1y1 = ng0.w;
    float n0x2 = ng1.x, n1x2 = ng1.y, n0y2 = ng1.z, n1y2 = ng1.w;
    float an0 = ng7.z, an1 = ng7.w;

    ull p0p[5];
#pragma unroll
    for (int k = 0; k < 5; k++) {
        float2 t = g_p0f2[((size_t)b * 5 + k) * HW_ + hwn];
        p0p[k] = pk(t.x, t.y);
    }

    ull acc0p[5], acc1p[5], sm0p[5], sm1p[5];
#pragma unroll
    for (int k = 0; k < 5; k++) { acc0p[k] = 0; acc1p[k] = 0; sm0p[k] = 0; sm1p[k] = 0; }

    const float4* gb = g_bev4 + (size_t)b * 2 * HW_ + h * 512;
    const float4* gp = g_pc4 + (size_t)b * 8 * HW_ + h * 512;

    // prefetch tile 0
    {
        uint32_t sba = (uint32_t)__cvta_generic_to_shared(&sb[0][0]);
        uint32_t spa = (uint32_t)__cvta_generic_to_shared(&sp[0][0]);
#pragma unroll
        for (int g = 0; g < 2; g++)
            cpasync16(sba + (g * TILE + tid) * 16, gb + g * HW_ + tid);
#pragma unroll
        for (int g = 0; g < 8; g++)
            cpasync16(spa + (g * TILE + tid) * 16, gp + g * HW_ + tid);
        asm volatile("cp.async.commit_group;");
    }

    for (int t = 0; t < 4; t++) {
        if (t < 3) {
            int nb = (t + 1) & 1;
            uint32_t sba = (uint32_t)__cvta_generic_to_shared(&sb[nb][0]);
            uint32_t spa = (uint32_t)__cvta_generic_to_shared(&sp[nb][0]);
            int off = (t + 1) * TILE + tid;
#pragma unroll
            for (int g = 0; g < 2; g++)
                cpasync16(sba + (g * TILE + tid) * 16, gb + g * HW_ + off);
#pragma unroll
            for (int g = 0; g < 8; g++)
                cpasync16(spa + (g * TILE + tid) * 16, gp + g * HW_ + off);
            asm volatile("cp.async.commit_group;");
            asm volatile("cp.async.wait_group 1;");
        } else {
            asm volatile("cp.async.wait_group 0;");
        }
        __syncthreads();

        const float4*     SB = sb[t & 1];
        const ulonglong2* SP = sp[t & 1];
#pragma unroll 2
        for (int j = 0; j < 4; j++) {
            int m = lane + j * 32;
            float4 bg0 = SB[m];
            float4 bg1 = SB[TILE + m];
            float4 G7f = ((const float4*)SP)[7 * TILE + m];

            float q00 = iou1(n0x1, n0y1, n0x2, n0y2, an0, bg0.x, bg0.z, bg1.x, bg1.z, G7f.z);
            float q01 = iou1(n0x1, n0y1, n0x2, n0y2, an0, bg0.y, bg0.w, bg1.y, bg1.w, G7f.w);
            float q10 = iou1(n1x1, n1y1, n1x2, n1y2, an1, bg0.x, bg0.z, bg1.x, bg1.z, G7f.z);
            float q11 = iou1(n1x1, n1y1, n1x2, n1y2, an1, bg0.y, bg0.w, bg1.y, bg1.w, G7f.w);

            float e00 = ex2(q00), e01 = ex2(q01);
            float e10 = ex2(q10), e11 = ex2(q11);
            ull e00s = pk(e00, e00), e01s = pk(e01, e01);
            ull e10s = pk(e10, e10), e11s = pk(e11, e11);
            ull es0s = add2(e00s, e01s);
            ull es1s = add2(e10s, e11s);

            ulonglong2 G5 = SP[5 * TILE + m];
            ulonglong2 G6 = SP[6 * TILE + m];
            ull p1p[5] = { G5.x, G5.y, G6.x, G6.y, pk(G7f.x, G7f.y) };

#pragma unroll
            for (int k = 0; k < 5; k++) {
                ull tt = mul2(p0p[k], p1p[k]);
                float b0, b1; upk(tt, b0, b1);
                ull ebp = pk(ex2(b0), ex2(b1));

                ulonglong2 Wk = SP[k * TILE + m];
                ull s0p = fma2(e01s, Wk.y, mul2(e00s, Wk.x));
                ull s1p = fma2(e11s, Wk.y, mul2(e10s, Wk.x));
                acc0p[k] = fma2(ebp, s0p, acc0p[k]);
                acc1p[k] = fma2(ebp, s1p, acc1p[k]);
                sm0p[k]  = fma2(ebp, es0s, sm0p[k]);
                sm1p[k]  = fma2(ebp, es1s, sm1p[k]);
            }
        }
        __syncthreads();
    }

    // warp butterfly reduction
#pragma unroll
    for (int o = 16; o > 0; o >>= 1) {
#pragma unroll
        for (int k = 0; k < 5; k++) {
            acc0p[k] = add2(acc0p[k], __shfl_xor_sync(0xffffffffu, acc0p[k], o));
            acc1p[k] = add2(acc1p[k], __shfl_xor_sync(0xffffffffu, acc1p[k], o));
            sm0p[k]  = add2(sm0p[k],  __shfl_xor_sync(0xffffffffu, sm0p[k],  o));
            sm1p[k]  = add2(sm1p[k],  __shfl_xor_sync(0xffffffffu, sm1p[k],  o));
        }
    }

    if (lane == 0) {
        ull* P = g_part + ((size_t)(h * NBOX + gw) * 5) * 4;
#pragma unroll
        for (int k = 0; k < 5; k++) {
            P[k * 4 + 0] = acc0p[k];
            P[k * 4 + 1] = acc1p[k];
            P[k * 4 + 2] = sm0p[k];
            P[k * 4 + 3] = sm1p[k];
        }
    }
    __syncthreads();

    // ---- combine: second arriver of this quad merges both halves ----
    if (tid == 0) {
        __threadfence();
        s_old = atomicAdd(&g_qctr[q], 1u);
    }
    __syncthreads();

    if (s_old == 1u) {
        if (tid == 0) {
            while (ld_acq(&g_ctr[1]) < N_SCS) __nanosleep(64);
        }
        __syncthreads();
        if (tid < 20) {
            int w = tid / 5;
            int k = tid - w * 5;
            int cell = q * 4 + w;
            int cb2 = cell >> 10;
            int hw2 = cell & (HW_ - 1);
            const ull* P0 = g_part + ((size_t)cell * 5 + k) * 4;
            const ull* P1 = P0 + (size_t)NBOX * 5 * 4;
            ull a0 = add2(P0[0], P1[0]);
            ull a1 = add2(P0[1], P1[1]);
            ull s0 = add2(P0[2], P1[2]);
            ull s1 = add2(P0[3], P1[3]);
            int c0 = 2 * k, c1 = 2 * k + 1;
            float i0 = g_scinv[cb2 * C_ + c0];
            float i1 = g_scinv[cb2 * C_ + c1];
            float v0, v1, d0, d1;
            upk(a0, v0, v1); upk(s0, d0, d1);
            out[((cb2 * A_ + 0) * C_ + c0) * HW_ + hw2] = v0 * rcpf(d0) * i0;
            out[((cb2 * A_ + 0) * C_ + c1) * HW_ + hw2] = v1 * rcpf(d1) * i1;
            upk(a1, v0, v1); upk(s1, d0, d1);
            out[((cb2 * A_ + 1) * C_ + c0) * HW_ + hw2] = v0 * rcpf(d0) * i0;
            out[((cb2 * A_ + 1) * C_ + c1) * HW_ + hw2] = v1 * rcpf(d1) * i1;
        }
        __syncthreads();
        if (tid == 0) g_qctr[q] = 0u;   // self-reset for next launch
    }

    // last compute block resets counters for the next launch. Safe: every
    // block increments ctr[2] only AFTER leaving its combine region, so when
    // the count hits N_COMP no block can still be waiting on ctr[1].
    if (tid == 0) {
        __threadfence();
        unsigned f = atomicAdd(&g_ctr[2], 1u);
        if (f == N_COMP - 1u) {
            g_ctr[1] = 0u;
            g_ctr[2] = 0u;
        }
    }
}

extern "C" void kernel_launch(void* const* d_in, const int* in_sizes, int n_in,
                              void* d_out, int out_size) {
    const float* scores = (const float*)d_in[0];
    const float* bbox = (const float*)d_in[1];
    const float* pp = (const float*)d_in[2];
    const float* dec = (const float*)d_in[3];
    float* out = (float*)d_out;

    k_prep<<<B_BEV, 128>>>(scores, pp, dec);
    k_main<<<L2_TOTAL, 128>>>(scores, bbox, pp, out);
}